// round 15
// baseline (speedup 1.0000x reference)
#include <cuda_runtime.h>
#include <cuda_fp16.h>
#include <cstdint>

#define NMAX 100000
#define EMAX 1600000
#define SCAN_B 1024
#define MAXBLK 128   // >= ceil(NMAX/SCAN_B) = 98

// Scratch (allocation-free rule: __device__ globals).
__device__ __half g_H1[(size_t)NMAX * 128];  // x @ W1 (fp16 storage)
__device__ __half g_H2[(size_t)NMAX * 40];   // hidden @ W2 (fp16 storage)
__device__ float g_dinv[NMAX];
__device__ int   g_deg[NMAX];                // in-degree (no self loop)
__device__ int   g_off[NMAX + 1];            // CSR row offsets (by dst)
__device__ int   g_pos[NMAX];                // bucket cursors
__device__ int2  g_edge[EMAX];               // {src, bits(nrm)} per CSR slot
__device__ unsigned long long g_flag[MAXBLK];// lookback: (inclusive<<1)|1

__device__ __forceinline__ float to_tf32(float f) {
    uint32_t u;
    asm("cvt.rna.tf32.f32 %0, %1;" : "=r"(u) : "f"(f));
    return __uint_as_float(u);
}

// ---------------------------------------------------------------------------
// Degree count, 4 edges per thread. Block 0 also zeroes lookback flags
// (visible to k_scan via stream ordering; resets state for graph replay).
// ---------------------------------------------------------------------------
__global__ void k_deg_count(const int* __restrict__ dst, int E, int n) {
    if (blockIdx.x == 0 && threadIdx.x < MAXBLK) g_flag[threadIdx.x] = 0ULL;
    int t = blockIdx.x * blockDim.x + threadIdx.x;
    int e0 = t * 4;
    if (e0 + 3 < E) {
        int4 d4 = *(const int4*)(dst + e0);
        if ((unsigned)d4.x < (unsigned)n) atomicAdd(&g_deg[d4.x], 1);
        if ((unsigned)d4.y < (unsigned)n) atomicAdd(&g_deg[d4.y], 1);
        if ((unsigned)d4.z < (unsigned)n) atomicAdd(&g_deg[d4.z], 1);
        if ((unsigned)d4.w < (unsigned)n) atomicAdd(&g_deg[d4.w], 1);
    } else {
        for (int e = e0; e < E; e++) {
            int d = dst[e];
            if ((unsigned)d < (unsigned)n) atomicAdd(&g_deg[d], 1);
        }
    }
}

// ---------------------------------------------------------------------------
// Single-pass exclusive scan (decoupled lookback). 98 blocks, all resident.
// Writes g_off, g_pos, g_dinv; last block writes g_off[n].
// ---------------------------------------------------------------------------
__global__ void k_scan(int n) {
    __shared__ int sh[SCAN_B];
    __shared__ unsigned long long sPrefix;
    int tid = threadIdx.x;
    int bid = blockIdx.x;
    int i = bid * SCAN_B + tid;
    int v = (i < n) ? g_deg[i] : 0;
    sh[tid] = v;
    __syncthreads();
    for (int off = 1; off < SCAN_B; off <<= 1) {
        int t = (tid >= off) ? sh[tid - off] : 0;
        __syncthreads();
        sh[tid] += t;
        __syncthreads();
    }

    if (tid == 0) {
        unsigned long long agg = (unsigned long long)sh[SCAN_B - 1];
        unsigned long long incl;
        if (bid == 0) {
            incl = agg;
        } else {
            unsigned long long f;
            do { f = atomicAdd(&g_flag[bid - 1], 0ULL); } while (!(f & 1ULL));
            incl = (f >> 1) + agg;
        }
        atomicExch(&g_flag[bid], (incl << 1) | 1ULL);
        sPrefix = incl - agg;
        if (bid == (int)gridDim.x - 1) g_off[n] = (int)incl;
    }
    __syncthreads();
    int prefix = (int)sPrefix;

    if (i < n) {
        int o = prefix + sh[tid] - v;   // exclusive
        g_off[i] = o;
        g_pos[i] = o;
        g_dinv[i] = rsqrtf((float)(v + 1));  // +1 self loop
    }
}

__global__ void k_bucket(const int* __restrict__ src,
                         const int* __restrict__ dst, int E, int n) {
    int e = blockIdx.x * blockDim.x + threadIdx.x;
    if (e >= E) return;
    int s = src[e], d = dst[e];
    if ((unsigned)s >= (unsigned)n || (unsigned)d >= (unsigned)n) return;
    float nrm = g_dinv[s] * g_dinv[d];
    int p = atomicAdd(&g_pos[d], 1);
    g_edge[p] = make_int2(s, __float_as_int(nrm));
}

// ---------------------------------------------------------------------------
// GEMM1 (tf32 tensor cores): g_H1[n,128] = X[n,128] @ W1[128,128], fp16 out.
// ---------------------------------------------------------------------------
__global__ void k_gemm1(const float* __restrict__ X, const float* __restrict__ W,
                        int n) {
    __shared__ float Xs[128][36];   // [row][kk]
    __shared__ float Ws[32][132];   // [kk][n]
    int tid = threadIdx.x;
    int warp = tid >> 5, lane = tid & 31;
    int rowBase = blockIdx.x * 128;
    int r0 = warp * 16;

    float c[16][4];
#pragma unroll
    for (int t = 0; t < 16; t++)
#pragma unroll
        for (int q = 0; q < 4; q++) c[t][q] = 0.f;

    for (int k0 = 0; k0 < 128; k0 += 32) {
        for (int i = tid; i < 1024; i += 256) {
            int row = i >> 3, c4 = (i & 7) * 4;
            int grow = rowBase + row;
            float4 v = make_float4(0.f, 0.f, 0.f, 0.f);
            if (grow < n) v = *(const float4*)&X[(size_t)grow * 128 + k0 + c4];
            Xs[row][c4 + 0] = to_tf32(v.x);
            Xs[row][c4 + 1] = to_tf32(v.y);
            Xs[row][c4 + 2] = to_tf32(v.z);
            Xs[row][c4 + 3] = to_tf32(v.w);
        }
        for (int i = tid; i < 1024; i += 256) {
            int k = i >> 5, n4 = (i & 31) * 4;
            float4 v = *(const float4*)&W[(size_t)(k0 + k) * 128 + n4];
            Ws[k][n4 + 0] = to_tf32(v.x);
            Ws[k][n4 + 1] = to_tf32(v.y);
            Ws[k][n4 + 2] = to_tf32(v.z);
            Ws[k][n4 + 3] = to_tf32(v.w);
        }
        __syncthreads();

        int qr = lane >> 2, qc = lane & 3;
#pragma unroll
        for (int ks = 0; ks < 32; ks += 8) {
            uint32_t a0 = __float_as_uint(Xs[r0 + qr][ks + qc]);
            uint32_t a1 = __float_as_uint(Xs[r0 + qr + 8][ks + qc]);
            uint32_t a2 = __float_as_uint(Xs[r0 + qr][ks + qc + 4]);
            uint32_t a3 = __float_as_uint(Xs[r0 + qr + 8][ks + qc + 4]);
#pragma unroll
            for (int nt = 0; nt < 16; nt++) {
                uint32_t b0 = __float_as_uint(Ws[ks + qc][nt * 8 + qr]);
                uint32_t b1 = __float_as_uint(Ws[ks + qc + 4][nt * 8 + qr]);
                asm volatile(
                    "mma.sync.aligned.m16n8k8.row.col.f32.tf32.tf32.f32 "
                    "{%0,%1,%2,%3}, {%4,%5,%6,%7}, {%8,%9}, {%0,%1,%2,%3};"
                    : "+f"(c[nt][0]), "+f"(c[nt][1]), "+f"(c[nt][2]), "+f"(c[nt][3])
                    : "r"(a0), "r"(a1), "r"(a2), "r"(a3), "r"(b0), "r"(b1));
            }
        }
        __syncthreads();
    }

    int qr = lane >> 2, qc = lane & 3;
    int row0 = rowBase + r0 + qr;
    int row1 = row0 + 8;
    __half2* H1h2 = (__half2*)g_H1;
#pragma unroll
    for (int nt = 0; nt < 16; nt++) {
        int col = nt * 8 + qc * 2;  // even
        if (row0 < n) H1h2[(size_t)row0 * 64 + (col >> 1)] = __floats2half2_rn(c[nt][0], c[nt][1]);
        if (row1 < n) H1h2[(size_t)row1 * 64 + (col >> 1)] = __floats2half2_rn(c[nt][2], c[nt][3]);
    }
}

// ---------------------------------------------------------------------------
// GEMM2 (tf32): g_H2[rows,40] = hidden[rows,128] @ W2, over [rowStart,rowEnd).
// ---------------------------------------------------------------------------
__global__ void k_gemm2(const float* __restrict__ Hin, const float* __restrict__ W2,
                        int rowStart, int rowEnd) {
    __shared__ float Xs[128][36];   // [row][kk]
    __shared__ float Ws[32][44];    // [kk][col<40]
    int tid = threadIdx.x;
    int warp = tid >> 5, lane = tid & 31;
    int rowBase = rowStart + blockIdx.x * 128;
    int r0 = warp * 16;

    float c[5][4];
#pragma unroll
    for (int t = 0; t < 5; t++)
#pragma unroll
        for (int q = 0; q < 4; q++) c[t][q] = 0.f;

    for (int k0 = 0; k0 < 128; k0 += 32) {
        for (int i = tid; i < 1024; i += 256) {
            int row = i >> 3, c4 = (i & 7) * 4;
            int grow = rowBase + row;
            float4 v = make_float4(0.f, 0.f, 0.f, 0.f);
            if (grow < rowEnd) v = *(const float4*)&Hin[(size_t)grow * 128 + k0 + c4];
            Xs[row][c4 + 0] = to_tf32(v.x);
            Xs[row][c4 + 1] = to_tf32(v.y);
            Xs[row][c4 + 2] = to_tf32(v.z);
            Xs[row][c4 + 3] = to_tf32(v.w);
        }
        for (int i = tid; i < 320; i += 256) {
            int k = i / 10, c4 = (i - k * 10) * 4;
            float4 v = *(const float4*)&W2[(size_t)(k0 + k) * 40 + c4];
            Ws[k][c4 + 0] = to_tf32(v.x);
            Ws[k][c4 + 1] = to_tf32(v.y);
            Ws[k][c4 + 2] = to_tf32(v.z);
            Ws[k][c4 + 3] = to_tf32(v.w);
        }
        __syncthreads();

        int qr = lane >> 2, qc = lane & 3;
#pragma unroll
        for (int ks = 0; ks < 32; ks += 8) {
            uint32_t a0 = __float_as_uint(Xs[r0 + qr][ks + qc]);
            uint32_t a1 = __float_as_uint(Xs[r0 + qr + 8][ks + qc]);
            uint32_t a2 = __float_as_uint(Xs[r0 + qr][ks + qc + 4]);
            uint32_t a3 = __float_as_uint(Xs[r0 + qr + 8][ks + qc + 4]);
#pragma unroll
            for (int nt = 0; nt < 5; nt++) {
                uint32_t b0 = __float_as_uint(Ws[ks + qc][nt * 8 + qr]);
                uint32_t b1 = __float_as_uint(Ws[ks + qc + 4][nt * 8 + qr]);
                asm volatile(
                    "mma.sync.aligned.m16n8k8.row.col.f32.tf32.tf32.f32 "
                    "{%0,%1,%2,%3}, {%4,%5,%6,%7}, {%8,%9}, {%0,%1,%2,%3};"
                    : "+f"(c[nt][0]), "+f"(c[nt][1]), "+f"(c[nt][2]), "+f"(c[nt][3])
                    : "r"(a0), "r"(a1), "r"(a2), "r"(a3), "r"(b0), "r"(b1));
            }
        }
        __syncthreads();
    }

    int qr = lane >> 2, qc = lane & 3;
    int row0 = rowBase + r0 + qr;
    int row1 = row0 + 8;
    __half2* H2h2 = (__half2*)g_H2;
#pragma unroll
    for (int nt = 0; nt < 5; nt++) {
        int col = nt * 8 + qc * 2;  // even
        if (row0 < rowEnd) H2h2[(size_t)row0 * 20 + (col >> 1)] = __floats2half2_rn(c[nt][0], c[nt][1]);
        if (row1 < rowEnd) H2h2[(size_t)row1 * 20 + (col >> 1)] = __floats2half2_rn(c[nt][2], c[nt][3]);
    }
}

// ---------------------------------------------------------------------------
// Gather layer 1 over node range [ns, ne): warp per dst node, MLP=4.
// ---------------------------------------------------------------------------
__device__ __forceinline__ float4 h1_row4(const uint2* H1, int row, int lane) {
    uint2 u = H1[(size_t)row * 32 + lane];
    float2 f0 = __half22float2(*(__half2*)&u.x);
    float2 f1 = __half22float2(*(__half2*)&u.y);
    return make_float4(f0.x, f0.y, f1.x, f1.y);
}

__device__ __forceinline__ void fma4(float4& a, float4 v, float nz) {
    a.x = fmaf(v.x, nz, a.x);
    a.y = fmaf(v.y, nz, a.y);
    a.z = fmaf(v.z, nz, a.z);
    a.w = fmaf(v.w, nz, a.w);
}

__global__ void k_gather1(const float* __restrict__ b1, float* __restrict__ out,
                          int ns, int ne) {
    int d = ns + ((blockIdx.x * blockDim.x + threadIdx.x) >> 5);
    int lane = threadIdx.x & 31;
    if (d >= ne) return;
    float dd = g_dinv[d];
    const uint2* H1 = (const uint2*)g_H1;

    float4 v = h1_row4(H1, d, lane);
    float sl = dd * dd;
    float4 a0 = make_float4(v.x * sl, v.y * sl, v.z * sl, v.w * sl);
    float4 a1 = make_float4(0.f, 0.f, 0.f, 0.f);
    float4 a2 = make_float4(0.f, 0.f, 0.f, 0.f);
    float4 a3 = make_float4(0.f, 0.f, 0.f, 0.f);

    int start = g_off[d], end = g_off[d + 1];
    for (int base = start; base < end; base += 32) {
        int idx = base + lane;
        int2 ev = (idx < end) ? g_edge[idx] : make_int2(0, 0);
        int   sv = ev.x;
        float nv = __int_as_float(ev.y);
        int cnt = end - base; if (cnt > 32) cnt = 32;
        int j = 0;
        for (; j + 3 < cnt; j += 4) {
            int   s0 = __shfl_sync(0xffffffffu, sv, j);
            int   s1 = __shfl_sync(0xffffffffu, sv, j + 1);
            int   s2 = __shfl_sync(0xffffffffu, sv, j + 2);
            int   s3 = __shfl_sync(0xffffffffu, sv, j + 3);
            float n0 = __shfl_sync(0xffffffffu, nv, j);
            float n1 = __shfl_sync(0xffffffffu, nv, j + 1);
            float n2 = __shfl_sync(0xffffffffu, nv, j + 2);
            float n3 = __shfl_sync(0xffffffffu, nv, j + 3);
            float4 v0 = h1_row4(H1, s0, lane);
            float4 v1 = h1_row4(H1, s1, lane);
            float4 v2 = h1_row4(H1, s2, lane);
            float4 v3 = h1_row4(H1, s3, lane);
            fma4(a0, v0, n0);
            fma4(a1, v1, n1);
            fma4(a2, v2, n2);
            fma4(a3, v3, n3);
        }
        for (; j < cnt; j++) {
            int   s0 = __shfl_sync(0xffffffffu, sv, j);
            float n0 = __shfl_sync(0xffffffffu, nv, j);
            float4 v0 = h1_row4(H1, s0, lane);
            fma4(a0, v0, n0);
        }
    }
    a0.x += a1.x + a2.x + a3.x;
    a0.y += a1.y + a2.y + a3.y;
    a0.z += a1.z + a2.z + a3.z;
    a0.w += a1.w + a2.w + a3.w;

    float4 bv = ((const float4*)b1)[lane];
    a0.x = fmaxf(a0.x + bv.x, 0.f);
    a0.y = fmaxf(a0.y + bv.y, 0.f);
    a0.z = fmaxf(a0.z + bv.z, 0.f);
    a0.w = fmaxf(a0.w + bv.w, 0.f);

    ((float4*)out)[(size_t)d * 32 + lane] = a0;
}

// ---------------------------------------------------------------------------
// Gather layer 2: warp per dst; lanes 0..19 hold one half2 -> float2 (40 cols).
// ---------------------------------------------------------------------------
__global__ void k_gather2(const float* __restrict__ b2, float* __restrict__ out,
                          int n) {
    int w = (blockIdx.x * blockDim.x + threadIdx.x) >> 5;
    int lane = threadIdx.x & 31;
    if (w >= n) return;
    int d = w;
    bool act = lane < 20;
    float dd = g_dinv[d];
    const __half2* H2 = (const __half2*)g_H2;

    float2 acc = make_float2(0.f, 0.f);
    float2 accB = make_float2(0.f, 0.f);
    if (act) {
        float2 v = __half22float2(H2[(size_t)d * 20 + lane]);
        float sl = dd * dd;
        acc.x = v.x * sl; acc.y = v.y * sl;
    }

    int start = g_off[d], end = g_off[d + 1];
    for (int base = start; base < end; base += 32) {
        int idx = base + lane;
        int2 ev = (idx < end) ? g_edge[idx] : make_int2(0, 0);
        int   sv = ev.x;
        float nv = __int_as_float(ev.y);
        int cnt = end - base; if (cnt > 32) cnt = 32;
        int j = 0;
        for (; j + 1 < cnt; j += 2) {
            int   s0 = __shfl_sync(0xffffffffu, sv, j);
            int   s1 = __shfl_sync(0xffffffffu, sv, j + 1);
            float n0 = __shfl_sync(0xffffffffu, nv, j);
            float n1 = __shfl_sync(0xffffffffu, nv, j + 1);
            if (act) {
                float2 v0 = __half22float2(H2[(size_t)s0 * 20 + lane]);
                float2 v1 = __half22float2(H2[(size_t)s1 * 20 + lane]);
                acc.x  = fmaf(v0.x, n0, acc.x);
                acc.y  = fmaf(v0.y, n0, acc.y);
                accB.x = fmaf(v1.x, n1, accB.x);
                accB.y = fmaf(v1.y, n1, accB.y);
            }
        }
        if (j < cnt) {
            int   s0 = __shfl_sync(0xffffffffu, sv, j);
            float n0 = __shfl_sync(0xffffffffu, nv, j);
            if (act) {
                float2 v0 = __half22float2(H2[(size_t)s0 * 20 + lane]);
                acc.x = fmaf(v0.x, n0, acc.x);
                acc.y = fmaf(v0.y, n0, acc.y);
            }
        }
    }

    if (act) {
        acc.x += accB.x; acc.y += accB.y;
        float2 bv = ((const float2*)b2)[lane];
        acc.x += bv.x; acc.y += bv.y;
        ((float2*)out)[(size_t)d * 20 + lane] = acc;
    }
}

// ---------------------------------------------------------------------------
extern "C" void kernel_launch(void* const* d_in, const int* in_sizes, int n_in,
                              void* d_out, int out_size) {
    (void)n_in; (void)out_size;
    const float* x  = (const float*)d_in[0];
    const int*   ei = (const int*)d_in[1];     // int32 edge index
    const float* W1 = (const float*)d_in[2];
    const float* b1 = (const float*)d_in[3];
    const float* W2 = (const float*)d_in[4];
    const float* b2 = (const float*)d_in[5];

    int n = in_sizes[0] / 128;
    int E = in_sizes[1] / 2;
    const int* src = ei;
    const int* dst = ei + E;

    float* logits = (float*)d_out;                    // [n, 40]
    float* hidden = logits + (size_t)n * 40;          // [n, 128]

    const int B = 256;
    int nscan = (n + SCAN_B - 1) / SCAN_B;
    int n2 = ((n / 2) + 127) & ~127;                  // split point (gemm2-tile aligned)
    if (n2 > n) n2 = n;

    void* degPtr = nullptr;
    cudaGetSymbolAddress(&degPtr, g_deg);

    cudaStream_t s1;
    cudaStreamCreateWithFlags(&s1, cudaStreamNonBlocking);
    cudaEvent_t evFork, evJoin, evCSR, evB;
    cudaEventCreateWithFlags(&evFork, cudaEventDisableTiming);
    cudaEventCreateWithFlags(&evJoin, cudaEventDisableTiming);
    cudaEventCreateWithFlags(&evCSR, cudaEventDisableTiming);
    cudaEventCreateWithFlags(&evB, cudaEventDisableTiming);

    // Side stream: gemm1
    cudaEventRecord(evFork, 0);
    cudaStreamWaitEvent(s1, evFork, 0);
    k_gemm1<<<(n + 127) / 128, B, 0, s1>>>(x, W1, n);
    cudaEventRecord(evJoin, s1);

    // Main stream: CSR build (memset -> deg -> single-pass scan -> bucket)
    cudaMemsetAsync(degPtr, 0, (size_t)n * sizeof(int));
    k_deg_count<<<((E + 3) / 4 + B - 1) / B, B>>>(dst, E, n);
    k_scan<<<nscan, SCAN_B>>>(n);
    k_bucket<<<(E + B - 1) / B, B>>>(src, dst, E, n);
    cudaEventRecord(evCSR, 0);

    // Side stream: gather1 upper half (after gemm1 [same stream] + CSR)
    cudaStreamWaitEvent(s1, evCSR, 0);
    if (n2 < n) {
        int warps = n - n2;
        k_gather1<<<(warps * 32 + B - 1) / B, B, 0, s1>>>(b1, hidden, n2, n);
    }
    cudaEventRecord(evB, s1);

    // Main stream: gather1 lower half (after gemm1), then gemm2 lower
    cudaStreamWaitEvent(0, evJoin, 0);
    if (n2 > 0) {
        k_gather1<<<(n2 * 32 + B - 1) / B, B>>>(b1, hidden, 0, n2);
        k_gemm2<<<(n2 + 127) / 128, B>>>(hidden, W2, 0, n2);
    }

    // Join upper half, finish gemm2, then gather2 -> logits
    cudaStreamWaitEvent(0, evB, 0);
    if (n2 < n) {
        k_gemm2<<<(n - n2 + 127) / 128, B>>>(hidden, W2, n2, n);
    }
    k_gather2<<<(n * 32 + B - 1) / B, B>>>(b2, logits, n);

    cudaEventDestroy(evFork);
    cudaEventDestroy(evJoin);
    cudaEventDestroy(evCSR);
    cudaEventDestroy(evB);
    cudaStreamDestroy(s1);
}

// round 16
// speedup vs baseline: 1.2145x; 1.2145x over previous
#include <cuda_runtime.h>
#include <cuda_fp16.h>
#include <cstdint>

#define NMAX 100000
#define EMAX 1600000
#define SCAN_B 1024
#define MAXBLK 128   // >= ceil(NMAX/SCAN_B) = 98

// Scratch (allocation-free rule: __device__ globals).
__device__ __half g_H1[(size_t)NMAX * 128];  // x @ W1 (fp16 storage)
__device__ __half g_H2[(size_t)NMAX * 40];   // hidden @ W2 (fp16 storage)
__device__ float g_dinv[NMAX];
__device__ int   g_deg[NMAX];                // in-degree (no self loop)
__device__ int   g_off[NMAX + 1];            // CSR row offsets (by dst)
__device__ int   g_pos[NMAX];                // bucket cursors
__device__ int2  g_edge[EMAX];               // {src, bits(nrm)} per CSR slot
__device__ int   g_part[MAXBLK];             // scan partials
__device__ int   g_partx[MAXBLK];            // exclusive-scanned partials

__device__ __forceinline__ float to_tf32(float f) {
    uint32_t u;
    asm("cvt.rna.tf32.f32 %0, %1;" : "=r"(u) : "f"(f));
    return __uint_as_float(u);
}

// ---------------------------------------------------------------------------
// Degree count, 4 edges per thread (g_deg zeroed by cudaMemsetAsync)
// ---------------------------------------------------------------------------
__global__ void k_deg_count(const int* __restrict__ dst, int E, int n) {
    int t = blockIdx.x * blockDim.x + threadIdx.x;
    int e0 = t * 4;
    if (e0 + 3 < E) {
        int4 d4 = *(const int4*)(dst + e0);
        if ((unsigned)d4.x < (unsigned)n) atomicAdd(&g_deg[d4.x], 1);
        if ((unsigned)d4.y < (unsigned)n) atomicAdd(&g_deg[d4.y], 1);
        if ((unsigned)d4.z < (unsigned)n) atomicAdd(&g_deg[d4.z], 1);
        if ((unsigned)d4.w < (unsigned)n) atomicAdd(&g_deg[d4.w], 1);
    } else {
        for (int e = e0; e < E; e++) {
            int d = dst[e];
            if ((unsigned)d < (unsigned)n) atomicAdd(&g_deg[d], 1);
        }
    }
}

// ---------------------------------------------------------------------------
// CSR build: 3-kernel scan (robust under concurrent streams); dinv fused.
// ---------------------------------------------------------------------------
__global__ void k_scan1(int n) {
    __shared__ int sh[SCAN_B];
    int tid = threadIdx.x;
    int i = blockIdx.x * SCAN_B + tid;
    int v = (i < n) ? g_deg[i] : 0;
    sh[tid] = v;
    __syncthreads();
    for (int off = 1; off < SCAN_B; off <<= 1) {
        int t = (tid >= off) ? sh[tid - off] : 0;
        __syncthreads();
        sh[tid] += t;
        __syncthreads();
    }
    if (i < n) {
        g_off[i] = sh[tid] - v;              // block-local exclusive
        g_dinv[i] = rsqrtf((float)(v + 1));  // +1 self loop
    }
    if (tid == SCAN_B - 1) g_part[blockIdx.x] = sh[tid];
}

__global__ void k_scan2(int nblocks) {
    __shared__ int sh[MAXBLK];
    int tid = threadIdx.x;
    int v = (tid < nblocks) ? g_part[tid] : 0;
    sh[tid] = v;
    __syncthreads();
    for (int off = 1; off < MAXBLK; off <<= 1) {
        int t = (tid >= off) ? sh[tid - off] : 0;
        __syncthreads();
        sh[tid] += t;
        __syncthreads();
    }
    if (tid < nblocks) g_partx[tid] = sh[tid] - v;  // exclusive
}

__global__ void k_scan3(int n, int E) {
    int i = blockIdx.x * blockDim.x + threadIdx.x;
    if (i < n) {
        int o = g_off[i] + g_partx[i / SCAN_B];
        g_off[i] = o;
        g_pos[i] = o;
    }
    if (i == 0) g_off[n] = E;
}

// ---------------------------------------------------------------------------
// Bucket scatter, 4 edges per thread (int4 loads of src and dst).
// ---------------------------------------------------------------------------
__global__ void k_bucket(const int* __restrict__ src,
                         const int* __restrict__ dst, int E, int n) {
    int t = blockIdx.x * blockDim.x + threadIdx.x;
    int e0 = t * 4;
    if (e0 + 3 < E) {
        int4 s4 = *(const int4*)(src + e0);
        int4 d4 = *(const int4*)(dst + e0);
#pragma unroll
        for (int q = 0; q < 4; q++) {
            int s = (q == 0) ? s4.x : (q == 1) ? s4.y : (q == 2) ? s4.z : s4.w;
            int d = (q == 0) ? d4.x : (q == 1) ? d4.y : (q == 2) ? d4.z : d4.w;
            if ((unsigned)s < (unsigned)n && (unsigned)d < (unsigned)n) {
                float nrm = g_dinv[s] * g_dinv[d];
                int p = atomicAdd(&g_pos[d], 1);
                g_edge[p] = make_int2(s, __float_as_int(nrm));
            }
        }
    } else {
        for (int e = e0; e < E; e++) {
            int s = src[e], d = dst[e];
            if ((unsigned)s < (unsigned)n && (unsigned)d < (unsigned)n) {
                float nrm = g_dinv[s] * g_dinv[d];
                int p = atomicAdd(&g_pos[d], 1);
                g_edge[p] = make_int2(s, __float_as_int(nrm));
            }
        }
    }
}

// ---------------------------------------------------------------------------
// GEMM1 (tf32 tensor cores): g_H1[n,128] = X[n,128] @ W1[128,128], fp16 out.
// ---------------------------------------------------------------------------
__global__ void k_gemm1(const float* __restrict__ X, const float* __restrict__ W,
                        int n) {
    __shared__ float Xs[128][36];   // [row][kk]
    __shared__ float Ws[32][132];   // [kk][n]
    int tid = threadIdx.x;
    int warp = tid >> 5, lane = tid & 31;
    int rowBase = blockIdx.x * 128;
    int r0 = warp * 16;

    float c[16][4];
#pragma unroll
    for (int t = 0; t < 16; t++)
#pragma unroll
        for (int q = 0; q < 4; q++) c[t][q] = 0.f;

    for (int k0 = 0; k0 < 128; k0 += 32) {
        for (int i = tid; i < 1024; i += 256) {
            int row = i >> 3, c4 = (i & 7) * 4;
            int grow = rowBase + row;
            float4 v = make_float4(0.f, 0.f, 0.f, 0.f);
            if (grow < n) v = *(const float4*)&X[(size_t)grow * 128 + k0 + c4];
            Xs[row][c4 + 0] = to_tf32(v.x);
            Xs[row][c4 + 1] = to_tf32(v.y);
            Xs[row][c4 + 2] = to_tf32(v.z);
            Xs[row][c4 + 3] = to_tf32(v.w);
        }
        for (int i = tid; i < 1024; i += 256) {
            int k = i >> 5, n4 = (i & 31) * 4;
            float4 v = *(const float4*)&W[(size_t)(k0 + k) * 128 + n4];
            Ws[k][n4 + 0] = to_tf32(v.x);
            Ws[k][n4 + 1] = to_tf32(v.y);
            Ws[k][n4 + 2] = to_tf32(v.z);
            Ws[k][n4 + 3] = to_tf32(v.w);
        }
        __syncthreads();

        int qr = lane >> 2, qc = lane & 3;
#pragma unroll
        for (int ks = 0; ks < 32; ks += 8) {
            uint32_t a0 = __float_as_uint(Xs[r0 + qr][ks + qc]);
            uint32_t a1 = __float_as_uint(Xs[r0 + qr + 8][ks + qc]);
            uint32_t a2 = __float_as_uint(Xs[r0 + qr][ks + qc + 4]);
            uint32_t a3 = __float_as_uint(Xs[r0 + qr + 8][ks + qc + 4]);
#pragma unroll
            for (int nt = 0; nt < 16; nt++) {
                uint32_t b0 = __float_as_uint(Ws[ks + qc][nt * 8 + qr]);
                uint32_t b1 = __float_as_uint(Ws[ks + qc + 4][nt * 8 + qr]);
                asm volatile(
                    "mma.sync.aligned.m16n8k8.row.col.f32.tf32.tf32.f32 "
                    "{%0,%1,%2,%3}, {%4,%5,%6,%7}, {%8,%9}, {%0,%1,%2,%3};"
                    : "+f"(c[nt][0]), "+f"(c[nt][1]), "+f"(c[nt][2]), "+f"(c[nt][3])
                    : "r"(a0), "r"(a1), "r"(a2), "r"(a3), "r"(b0), "r"(b1));
            }
        }
        __syncthreads();
    }

    int qr = lane >> 2, qc = lane & 3;
    int row0 = rowBase + r0 + qr;
    int row1 = row0 + 8;
    __half2* H1h2 = (__half2*)g_H1;
#pragma unroll
    for (int nt = 0; nt < 16; nt++) {
        int col = nt * 8 + qc * 2;  // even
        if (row0 < n) H1h2[(size_t)row0 * 64 + (col >> 1)] = __floats2half2_rn(c[nt][0], c[nt][1]);
        if (row1 < n) H1h2[(size_t)row1 * 64 + (col >> 1)] = __floats2half2_rn(c[nt][2], c[nt][3]);
    }
}

// ---------------------------------------------------------------------------
// GEMM2 (tf32 tensor cores): g_H2[n,40] = hidden[n,128] @ W2[128,40], fp16 out.
// ---------------------------------------------------------------------------
__global__ void k_gemm2(const float* __restrict__ Hin, const float* __restrict__ W2,
                        int n) {
    __shared__ float Xs[128][36];   // [row][kk]
    __shared__ float Ws[32][44];    // [kk][col<40]
    int tid = threadIdx.x;
    int warp = tid >> 5, lane = tid & 31;
    int rowBase = blockIdx.x * 128;
    int r0 = warp * 16;

    float c[5][4];
#pragma unroll
    for (int t = 0; t < 5; t++)
#pragma unroll
        for (int q = 0; q < 4; q++) c[t][q] = 0.f;

    for (int k0 = 0; k0 < 128; k0 += 32) {
        for (int i = tid; i < 1024; i += 256) {
            int row = i >> 3, c4 = (i & 7) * 4;
            int grow = rowBase + row;
            float4 v = make_float4(0.f, 0.f, 0.f, 0.f);
            if (grow < n) v = *(const float4*)&Hin[(size_t)grow * 128 + k0 + c4];
            Xs[row][c4 + 0] = to_tf32(v.x);
            Xs[row][c4 + 1] = to_tf32(v.y);
            Xs[row][c4 + 2] = to_tf32(v.z);
            Xs[row][c4 + 3] = to_tf32(v.w);
        }
        for (int i = tid; i < 320; i += 256) {
            int k = i / 10, c4 = (i - k * 10) * 4;
            float4 v = *(const float4*)&W2[(size_t)(k0 + k) * 40 + c4];
            Ws[k][c4 + 0] = to_tf32(v.x);
            Ws[k][c4 + 1] = to_tf32(v.y);
            Ws[k][c4 + 2] = to_tf32(v.z);
            Ws[k][c4 + 3] = to_tf32(v.w);
        }
        __syncthreads();

        int qr = lane >> 2, qc = lane & 3;
#pragma unroll
        for (int ks = 0; ks < 32; ks += 8) {
            uint32_t a0 = __float_as_uint(Xs[r0 + qr][ks + qc]);
            uint32_t a1 = __float_as_uint(Xs[r0 + qr + 8][ks + qc]);
            uint32_t a2 = __float_as_uint(Xs[r0 + qr][ks + qc + 4]);
            uint32_t a3 = __float_as_uint(Xs[r0 + qr + 8][ks + qc + 4]);
#pragma unroll
            for (int nt = 0; nt < 5; nt++) {
                uint32_t b0 = __float_as_uint(Ws[ks + qc][nt * 8 + qr]);
                uint32_t b1 = __float_as_uint(Ws[ks + qc + 4][nt * 8 + qr]);
                asm volatile(
                    "mma.sync.aligned.m16n8k8.row.col.f32.tf32.tf32.f32 "
                    "{%0,%1,%2,%3}, {%4,%5,%6,%7}, {%8,%9}, {%0,%1,%2,%3};"
                    : "+f"(c[nt][0]), "+f"(c[nt][1]), "+f"(c[nt][2]), "+f"(c[nt][3])
                    : "r"(a0), "r"(a1), "r"(a2), "r"(a3), "r"(b0), "r"(b1));
            }
        }
        __syncthreads();
    }

    int qr = lane >> 2, qc = lane & 3;
    int row0 = rowBase + r0 + qr;
    int row1 = row0 + 8;
    __half2* H2h2 = (__half2*)g_H2;
#pragma unroll
    for (int nt = 0; nt < 5; nt++) {
        int col = nt * 8 + qc * 2;  // even
        if (row0 < n) H2h2[(size_t)row0 * 20 + (col >> 1)] = __floats2half2_rn(c[nt][0], c[nt][1]);
        if (row1 < n) H2h2[(size_t)row1 * 20 + (col >> 1)] = __floats2half2_rn(c[nt][2], c[nt][3]);
    }
}

// ---------------------------------------------------------------------------
// Gather layer 1: warp per dst node; 4 independent accumulator chains (MLP=4).
// ---------------------------------------------------------------------------
__device__ __forceinline__ float4 h1_row4(const uint2* H1, int row, int lane) {
    uint2 u = H1[(size_t)row * 32 + lane];
    float2 f0 = __half22float2(*(__half2*)&u.x);
    float2 f1 = __half22float2(*(__half2*)&u.y);
    return make_float4(f0.x, f0.y, f1.x, f1.y);
}

__device__ __forceinline__ void fma4(float4& a, float4 v, float nz) {
    a.x = fmaf(v.x, nz, a.x);
    a.y = fmaf(v.y, nz, a.y);
    a.z = fmaf(v.z, nz, a.z);
    a.w = fmaf(v.w, nz, a.w);
}

__global__ void k_gather1(const float* __restrict__ b1, float* __restrict__ out,
                          int n) {
    int d = (blockIdx.x * blockDim.x + threadIdx.x) >> 5;
    int lane = threadIdx.x & 31;
    if (d >= n) return;
    float dd = g_dinv[d];
    const uint2* H1 = (const uint2*)g_H1;

    float4 v = h1_row4(H1, d, lane);
    float sl = dd * dd;
    float4 a0 = make_float4(v.x * sl, v.y * sl, v.z * sl, v.w * sl);
    float4 a1 = make_float4(0.f, 0.f, 0.f, 0.f);
    float4 a2 = make_float4(0.f, 0.f, 0.f, 0.f);
    float4 a3 = make_float4(0.f, 0.f, 0.f, 0.f);

    int start = g_off[d], end = g_off[d + 1];
    for (int base = start; base < end; base += 32) {
        int idx = base + lane;
        int2 ev = (idx < end) ? g_edge[idx] : make_int2(0, 0);
        int   sv = ev.x;
        float nv = __int_as_float(ev.y);
        int cnt = end - base; if (cnt > 32) cnt = 32;
        int j = 0;
        for (; j + 3 < cnt; j += 4) {
            int   s0 = __shfl_sync(0xffffffffu, sv, j);
            int   s1 = __shfl_sync(0xffffffffu, sv, j + 1);
            int   s2 = __shfl_sync(0xffffffffu, sv, j + 2);
            int   s3 = __shfl_sync(0xffffffffu, sv, j + 3);
            float n0 = __shfl_sync(0xffffffffu, nv, j);
            float n1 = __shfl_sync(0xffffffffu, nv, j + 1);
            float n2 = __shfl_sync(0xffffffffu, nv, j + 2);
            float n3 = __shfl_sync(0xffffffffu, nv, j + 3);
            float4 v0 = h1_row4(H1, s0, lane);
            float4 v1 = h1_row4(H1, s1, lane);
            float4 v2 = h1_row4(H1, s2, lane);
            float4 v3 = h1_row4(H1, s3, lane);
            fma4(a0, v0, n0);
            fma4(a1, v1, n1);
            fma4(a2, v2, n2);
            fma4(a3, v3, n3);
        }
        for (; j < cnt; j++) {
            int   s0 = __shfl_sync(0xffffffffu, sv, j);
            float n0 = __shfl_sync(0xffffffffu, nv, j);
            float4 v0 = h1_row4(H1, s0, lane);
            fma4(a0, v0, n0);
        }
    }
    a0.x += a1.x + a2.x + a3.x;
    a0.y += a1.y + a2.y + a3.y;
    a0.z += a1.z + a2.z + a3.z;
    a0.w += a1.w + a2.w + a3.w;

    float4 bv = ((const float4*)b1)[lane];
    a0.x = fmaxf(a0.x + bv.x, 0.f);
    a0.y = fmaxf(a0.y + bv.y, 0.f);
    a0.z = fmaxf(a0.z + bv.z, 0.f);
    a0.w = fmaxf(a0.w + bv.w, 0.f);

    ((float4*)out)[(size_t)d * 32 + lane] = a0;
}

// ---------------------------------------------------------------------------
// Gather layer 2: warp per dst; lanes 0..19 hold one half2 -> float2 (40 cols).
// ---------------------------------------------------------------------------
__global__ void k_gather2(const float* __restrict__ b2, float* __restrict__ out,
                          int n) {
    int w = (blockIdx.x * blockDim.x + threadIdx.x) >> 5;
    int lane = threadIdx.x & 31;
    if (w >= n) return;
    int d = w;
    bool act = lane < 20;
    float dd = g_dinv[d];
    const __half2* H2 = (const __half2*)g_H2;

    float2 acc = make_float2(0.f, 0.f);
    float2 accB = make_float2(0.f, 0.f);
    if (act) {
        float2 v = __half22float2(H2[(size_t)d * 20 + lane]);
        float sl = dd * dd;
        acc.x = v.x * sl; acc.y = v.y * sl;
    }

    int start = g_off[d], end = g_off[d + 1];
    for (int base = start; base < end; base += 32) {
        int idx = base + lane;
        int2 ev = (idx < end) ? g_edge[idx] : make_int2(0, 0);
        int   sv = ev.x;
        float nv = __int_as_float(ev.y);
        int cnt = end - base; if (cnt > 32) cnt = 32;
        int j = 0;
        for (; j + 1 < cnt; j += 2) {
            int   s0 = __shfl_sync(0xffffffffu, sv, j);
            int   s1 = __shfl_sync(0xffffffffu, sv, j + 1);
            float n0 = __shfl_sync(0xffffffffu, nv, j);
            float n1 = __shfl_sync(0xffffffffu, nv, j + 1);
            if (act) {
                float2 v0 = __half22float2(H2[(size_t)s0 * 20 + lane]);
                float2 v1 = __half22float2(H2[(size_t)s1 * 20 + lane]);
                acc.x  = fmaf(v0.x, n0, acc.x);
                acc.y  = fmaf(v0.y, n0, acc.y);
                accB.x = fmaf(v1.x, n1, accB.x);
                accB.y = fmaf(v1.y, n1, accB.y);
            }
        }
        if (j < cnt) {
            int   s0 = __shfl_sync(0xffffffffu, sv, j);
            float n0 = __shfl_sync(0xffffffffu, nv, j);
            if (act) {
                float2 v0 = __half22float2(H2[(size_t)s0 * 20 + lane]);
                acc.x = fmaf(v0.x, n0, acc.x);
                acc.y = fmaf(v0.y, n0, acc.y);
            }
        }
    }

    if (act) {
        acc.x += accB.x; acc.y += accB.y;
        float2 bv = ((const float2*)b2)[lane];
        acc.x += bv.x; acc.y += bv.y;
        ((float2*)out)[(size_t)d * 20 + lane] = acc;
    }
}

// ---------------------------------------------------------------------------
extern "C" void kernel_launch(void* const* d_in, const int* in_sizes, int n_in,
                              void* d_out, int out_size) {
    (void)n_in; (void)out_size;
    const float* x  = (const float*)d_in[0];
    const int*   ei = (const int*)d_in[1];     // int32 edge index
    const float* W1 = (const float*)d_in[2];
    const float* b1 = (const float*)d_in[3];
    const float* W2 = (const float*)d_in[4];
    const float* b2 = (const float*)d_in[5];

    int n = in_sizes[0] / 128;
    int E = in_sizes[1] / 2;
    const int* src = ei;
    const int* dst = ei + E;

    float* logits = (float*)d_out;                    // [n, 40]
    float* hidden = logits + (size_t)n * 40;          // [n, 128]

    const int B = 256;
    int nscan = (n + SCAN_B - 1) / SCAN_B;

    void* degPtr = nullptr;
    cudaGetSymbolAddress(&degPtr, g_deg);

    // Fork: gemm1 (side stream) overlaps the CSR build (main stream).
    cudaStream_t s1;
    cudaStreamCreateWithFlags(&s1, cudaStreamNonBlocking);
    cudaEvent_t evFork, evJoin;
    cudaEventCreateWithFlags(&evFork, cudaEventDisableTiming);
    cudaEventCreateWithFlags(&evJoin, cudaEventDisableTiming);

    cudaEventRecord(evFork, 0);
    cudaStreamWaitEvent(s1, evFork, 0);
    k_gemm1<<<(n + 127) / 128, B, 0, s1>>>(x, W1, n);
    cudaEventRecord(evJoin, s1);

    // Main stream: CSR build
    cudaMemsetAsync(degPtr, 0, (size_t)n * sizeof(int));
    k_deg_count<<<((E + 3) / 4 + B - 1) / B, B>>>(dst, E, n);
    k_scan1<<<nscan, SCAN_B>>>(n);
    k_scan2<<<1, MAXBLK>>>(nscan);
    k_scan3<<<(n + B - 1) / B, B>>>(n, E);
    k_bucket<<<((E + 3) / 4 + B - 1) / B, B>>>(src, dst, E, n);

    // Join, then gather1 (needs both CSR and g_H1)
    cudaStreamWaitEvent(0, evJoin, 0);
    k_gather1<<<(n * 32 + B - 1) / B, B>>>(b1, hidden, n);

    // Layer 2: tf32 tensor GEMM (fp16 out) then gather -> logits
    k_gemm2<<<(n + 127) / 128, B>>>(hidden, W2, n);
    k_gather2<<<(n * 32 + B - 1) / B, B>>>(b2, logits, n);

    cudaEventDestroy(evFork);
    cudaEventDestroy(evJoin);
    cudaStreamDestroy(s1);
}